// round 14
// baseline (speedup 1.0000x reference)
#include <cuda_runtime.h>
#include <cuda_bf16.h>
#include <cstdint>

#define NB 128
#define NT 128
#define NC 32
#define NH 128
#define NO 10
#define NCTA 128
#define NTHR 256
#define MAXSTEPS 64

#define W1PR 132
#define W2PR 68
#define H1PR 68
#define DXPR 36
#define OFF_W1S 0
#define OFF_W2HI 16896
#define OFF_W2LO 19072
#define OFF_H1HI 21248
#define OFF_H1LO 29952
#define OFF_DXS 38656
#define OFF_RED 43264
#define OFF_TS  43520
#define OFF_B1  43648
#define OFF_B2  43776
#define OFF_YS  43808
#define OFF_YC  43936
#define OFF_SC  44064
#define SMEM_FLOATS 44072
#define SMEM_BYTES (SMEM_FLOATS * 4)

__device__ __align__(16) float g_k[7][NB*NH];
__device__ __align__(16) unsigned g_H1hi[NB*64];
__device__ __align__(16) unsigned g_H1lo[NB*64];
__device__ __align__(16) float g_dX[7][NB*NC];
__device__ __align__(128) unsigned g_flags[NCTA*32];
__device__ unsigned g_ndone;

__constant__ float A_TAB[7][6] = {
  {0.f,0.f,0.f,0.f,0.f,0.f},
  {(float)(1.0/5.0),0.f,0.f,0.f,0.f,0.f},
  {(float)(3.0/40.0),(float)(9.0/40.0),0.f,0.f,0.f,0.f},
  {(float)(44.0/45.0),(float)(-56.0/15.0),(float)(32.0/9.0),0.f,0.f,0.f},
  {(float)(19372.0/6561.0),(float)(-25360.0/2187.0),(float)(64448.0/6561.0),(float)(-212.0/729.0),0.f,0.f},
  {(float)(9017.0/3168.0),(float)(-355.0/33.0),(float)(46732.0/5247.0),(float)(49.0/176.0),(float)(-5103.0/18656.0),0.f},
  {(float)(35.0/384.0),0.f,(float)(500.0/1113.0),(float)(125.0/192.0),(float)(-2187.0/6784.0),(float)(11.0/84.0)},
};
__constant__ float C_TAB[7] = {0.f,(float)(1.0/5.0),(float)(3.0/10.0),(float)(4.0/5.0),(float)(8.0/9.0),1.f,1.f};

#define E0 ((float)(71.0/57600.0))
#define E2 ((float)(-71.0/16695.0))
#define E3 ((float)(71.0/1920.0))
#define E4 ((float)(-17253.0/339200.0))
#define E5 ((float)(22.0/525.0))
#define E6 ((float)(-1.0/40.0))

__device__ __forceinline__ unsigned ld_u32_cg(const unsigned* p) {
  unsigned v; asm volatile("ld.global.cg.u32 %0, [%1];" : "=r"(v) : "l"(p)); return v;
}
__device__ __forceinline__ unsigned ld_acq(const unsigned* p) {
  unsigned v; asm volatile("ld.acquire.gpu.global.u32 %0, [%1];" : "=r"(v) : "l"(p)); return v;
}
__device__ __forceinline__ void st_u32_cg(unsigned* p, unsigned v) {
  asm volatile("st.global.cg.u32 [%0], %1;" :: "l"(p), "r"(v) : "memory");
}
__device__ __forceinline__ void pollflag(int idx, unsigned seq) {
  while ((int)(ld_acq(&g_flags[idx * 32]) - seq) < 0) { }
}
__device__ __forceinline__ float fast_tanh(float x) {
  x = fminf(fmaxf(x, -9.f), 9.f);
  float e = __expf(2.f * x);
  return __fdividef(e - 1.f, e + 1.f);
}
__device__ __forceinline__ uint32_t pack_bf16x2(float e0, float e1) {
  uint32_t d;
  asm("cvt.rn.bf16x2.f32 %0, %1, %2;" : "=r"(d) : "f"(e1), "f"(e0));
  return d;
}
__device__ __forceinline__ uint32_t smem_u32(const void* p) {
  uint32_t a;
  asm("{ .reg .u64 t; cvta.to.shared.u64 t, %1; cvt.u32.u64 %0, t; }" : "=r"(a) : "l"(p));
  return a;
}
__device__ __forceinline__ void mma_bf16(float* d, uint32_t a0, uint32_t a1, uint32_t a2, uint32_t a3,
                                         uint32_t b0, uint32_t b1) {
  asm volatile(
    "mma.sync.aligned.m16n8k16.row.col.f32.bf16.bf16.f32 "
    "{%0,%1,%2,%3}, {%4,%5,%6,%7}, {%8,%9}, {%0,%1,%2,%3};"
    : "+f"(d[0]), "+f"(d[1]), "+f"(d[2]), "+f"(d[3])
    : "r"(a0), "r"(a1), "r"(a2), "r"(a3), "r"(b0), "r"(b1));
}
__device__ __forceinline__ void ldmx4(uint32_t* r, uint32_t addr) {
  asm volatile("ldmatrix.sync.aligned.m8n8.x4.shared.b16 {%0,%1,%2,%3}, [%4];"
    : "=r"(r[0]), "=r"(r[1]), "=r"(r[2]), "=r"(r[3]) : "r"(addr));
}

__global__ __launch_bounds__(NTHR, 1)
void cde_kernel(const float* __restrict__ ts, const float* __restrict__ xs,
                const float* __restrict__ W1, const float* __restrict__ b1,
                const float* __restrict__ W2, const float* __restrict__ b2,
                const float* __restrict__ lin_w, const float* __restrict__ lin_b,
                float* __restrict__ out)
{
  extern __shared__ float sm[];
  float*    W1s  = sm + OFF_W1S;
  unsigned* W2hiS= (unsigned*)(sm + OFF_W2HI);
  unsigned* W2loS= (unsigned*)(sm + OFF_W2LO);
  unsigned* H1hiS= (unsigned*)(sm + OFF_H1HI);
  unsigned* H1loS= (unsigned*)(sm + OFF_H1LO);
  float*    dXs  = sm + OFF_DXS;
  float*    red  = sm + OFF_RED;
  float*    tss  = sm + OFF_TS;
  float*    b1s  = sm + OFF_B1;
  float*    b2s  = sm + OFF_B2;
  float*    Ysm  = sm + OFF_YS;
  float*    Ycur = sm + OFF_YC;
  float*    scal = sm + OFF_SC;

  const int tid = threadIdx.x;
  const int bid = blockIdx.x;
  const int wid = tid >> 5;
  const int lane = tid & 31;
  const int g = lane >> 2;
  const int q = lane & 3;
  const uint32_t smb = smem_u32(sm);

  const unsigned base_nd = ld_u32_cg(&g_ndone);
  unsigned seq = ld_u32_cg(&g_flags[bid * 32]);

  for (int i = tid; i < NH*NH; i += NTHR) { int h = i >> 7, k = i & 127; W1s[h*W1PR + k] = W1[i]; }
  for (int i = tid; i < 32*64; i += NTHR) {
    int c = i >> 6, kq = i & 63;
    float w0 = W2[bid*32*NH + c*NH + kq*2];
    float w1 = W2[bid*32*NH + c*NH + kq*2 + 1];
    __nv_bfloat16 h0 = __float2bfloat16(w0), h1 = __float2bfloat16(w1);
    W2hiS[c*W2PR + kq] = pack_bf16x2(w0, w1);
    W2loS[c*W2PR + kq] = pack_bf16x2(w0 - __bfloat162float(h0), w1 - __bfloat162float(h1));
  }
  for (int i = tid; i < NT; i += NTHR) tss[i] = ts[i];
  for (int i = tid; i < NH; i += NTHR) b1s[i] = b1[i];
  if (tid < 32) b2s[tid] = b2[bid*32 + tid];
  if (tid < NH) Ycur[tid] = 0.f;
  if (tid == 0) {
    float t0 = ts[0], te = ts[NT-1];
    scal[0] = t0; scal[1] = 0.01f; scal[2] = fminf(0.01f, te - t0);
  }
  __syncthreads();
  const float tEnd = tss[NT-1];
  const float* xb = xs + (size_t)bid*NT*NC;

  const int lrow = wid*16 + (lane & 7) + ((lane >> 3) & 1) * 8;
  const int lcol = ((lane >> 4) & 1) * 4;
  const uint32_t hibase = smb + (uint32_t)(OFF_H1HI + lrow*H1PR + lcol) * 4u;
  const uint32_t lobase = smb + (uint32_t)(OFF_H1LO + lrow*H1PR + lcol) * 4u;

  float yreg = 0.f;
  float ynew_r = 0.f;
  bool counted = false;
  bool exit_all = false;

  for (int step = 0; step < MAXSTEPS && !exit_all; step++) {
    const int sb = (step == 0) ? 0 : 1;   // FSAL
    const float tcur = scal[0];
    const float dt_c = scal[2];
    for (int s = sb; s < 7; s++) {
      // ======== phase A ========
      // tid>=128 at s==sb: local dX math (no cross-CTA deps) overlaps polls
      if (tid >= 128 && s == sb) {
        for (int i = tid - 128; i < (7 - sb) * NC; i += 128) {
          int sp = sb + i / NC;
          int c = i % NC;
          float tq = tcur + C_TAB[sp] * dt_c;
          int lo = 0, hi = NT;
          while (lo < hi) { int mid = (lo + hi) >> 1; if (tss[mid] <= tq) lo = mid + 1; else hi = mid; }
          int idx = lo - 1; if (idx < 0) idx = 0; if (idx > NT-2) idx = NT-2;
          float t0 = tss[idx], t1 = tss[idx+1];
          float hh = t1 - t0;
          float sfr = (tq - t0) / hh;
          float dh00 = 6.f*sfr*sfr - 6.f*sfr;
          float dh10 = 3.f*sfr*sfr - 4.f*sfr + 1.f;
          float dh11 = 3.f*sfr*sfr - 2.f*sfr;
          float x0 = __ldg(&xb[idx*NC + c]);
          float x1 = __ldg(&xb[(idx+1)*NC + c]);
          float mi1 = (x1 - x0) / hh;
          float mi;
          if (idx == 0) mi = (x1 - x0) / (tss[1] - tss[0]);
          else { float xm1 = __ldg(&xb[(idx-1)*NC + c]); mi = (x0 - xm1) / (tss[idx] - tss[idx-1]); }
          float dx = (dh00*x0 - dh00*x1) / hh + dh10*mi + dh11*mi1;
          __stcg(&g_dX[sp][bid*NC + c], dx);
        }
      }
      if (tid < NH) {
        // poll own producer (CTA tid) for k(s-1); trivial at first stage
        pollflag(tid, seq);
        float ysv;
        if (s == 0) ysv = yreg;
        else {
          float kv[6];
          #pragma unroll
          for (int j = 0; j < 6; j++)
            kv[j] = (j < s) ? __ldcg(&g_k[j][bid*NH + tid]) : 0.f;
          float acc = A_TAB[s][0] * kv[0];
          #pragma unroll
          for (int j = 1; j < 6; j++)
            acc = fmaf(A_TAB[s][j], kv[j], acc);
          ysv = yreg + dt_c * acc;
        }
        Ysm[tid] = ysv;
        if (s == 6) ynew_r = ysv;
      }
      __syncthreads();   // all 128 observations done -> collective reads safe
      if (s > sb) {
        for (int i = tid; i < (NB*NC)/4; i += NTHR) {
          int b = i >> 3, c4 = (i & 7) * 4;
          float4 u = __ldcg((const float4*)&g_dX[s][b*NC + c4]);
          *(float4*)&dXs[b*DXPR + c4] = u;
        }
      }
      {
        int h = tid & 127;
        int half = tid >> 7;
        const int kb = half * 64;
        float a0=0.f,a1=0.f,a2=0.f,a3=0.f;
        const float* wrow = &W1s[h*W1PR + kb];
        #pragma unroll 4
        for (int k = 0; k < 64; k += 4) {
          float4 wv = *(const float4*)&wrow[k];
          float4 yv = *(const float4*)&Ysm[kb + k];
          a0 = fmaf(wv.x, yv.x, a0);
          a1 = fmaf(wv.y, yv.y, a1);
          a2 = fmaf(wv.z, yv.z, a2);
          a3 = fmaf(wv.w, yv.w, a3);
        }
        red[half*NH + h] = (a0+a1)+(a2+a3);
      }
      __syncthreads();
      if (tid < 64) {
        float f0 = fmaxf(b1s[2*tid]   + red[2*tid]   + red[NH + 2*tid],   0.f);
        float f1 = fmaxf(b1s[2*tid+1] + red[2*tid+1] + red[NH + 2*tid+1], 0.f);
        uint32_t hi = pack_bf16x2(f0, f1);
        __nv_bfloat162 hb = *reinterpret_cast<__nv_bfloat162*>(&hi);
        uint32_t lo = pack_bf16x2(f0 - __bfloat162float(hb.x), f1 - __bfloat162float(hb.y));
        st_u32_cg(&g_H1hi[bid*64 + tid], hi);
        st_u32_cg(&g_H1lo[bid*64 + tid], lo);
      }
      // publish H1-ready
      __syncthreads();
      ++seq;
      if (tid == 0) { __threadfence(); st_u32_cg(&g_flags[bid*32], seq); }

      // ======== phase B ========
      {
        // per-producer pipelined staging: thread tid stages batch tid
        if (tid < 128) {
          pollflag(tid, seq);
          const unsigned* shi = g_H1hi + tid*64;
          const unsigned* slo = g_H1lo + tid*64;
          unsigned* dhi = H1hiS + tid*H1PR;
          unsigned* dlo = H1loS + tid*H1PR;
          #pragma unroll
          for (int j2 = 0; j2 < 16; j2++) {
            *(uint4*)&dhi[j2*4] = __ldcg((const uint4*)shi + j2);
            *(uint4*)&dlo[j2*4] = __ldcg((const uint4*)slo + j2);
          }
        }
        __syncthreads();   // all H1(s) flags observed collectively
        if (s == sb) {
          for (int i = tid; i < (NB*NC)/4; i += NTHR) {
            int b = i >> 3, c4 = (i & 7) * 4;
            float4 u = __ldcg((const float4*)&g_dX[s][b*NC + c4]);
            *(float4*)&dXs[b*DXPR + c4] = u;
          }
          // early-exit agreement point (all step-(N-1) increments visible; stable)
          if (tid == 0) scal[4] = (float)(ld_u32_cg(&g_ndone) - base_nd);
          __syncthreads();
          if (scal[4] == (float)NB) { exit_all = true; break; }
        }

        const int mb = wid * 16;
        float d[4][4];
        #pragma unroll
        for (int nt = 0; nt < 4; nt++)
          #pragma unroll
          for (int r = 0; r < 4; r++) d[nt][r] = 0.f;

        #pragma unroll
        for (int kk = 0; kk < 8; kk++) {
          const int kq = kk*8 + q;
          uint32_t ah[4], al[4];
          ldmx4(ah, hibase + (uint32_t)kk * 32u);
          ldmx4(al, lobase + (uint32_t)kk * 32u);
          #pragma unroll
          for (int nt = 0; nt < 4; nt++) {
            const int c = nt*8 + g;
            uint32_t bh0 = W2hiS[c*W2PR + kq];
            uint32_t bh1 = W2hiS[c*W2PR + kq + 4];
            uint32_t bl0 = W2loS[c*W2PR + kq];
            uint32_t bl1 = W2loS[c*W2PR + kq + 4];
            mma_bf16(d[nt], ah[0], ah[1], ah[2], ah[3], bh0, bh1);
            mma_bf16(d[nt], al[0], al[1], al[2], al[3], bh0, bh1);
            mma_bf16(d[nt], ah[0], ah[1], ah[2], ah[3], bl0, bl1);
          }
        }

        float part0 = 0.f, part1 = 0.f;
        const int row0 = mb + g, row1 = mb + g + 8;
        #pragma unroll
        for (int nt = 0; nt < 4; nt++) {
          const int cb = nt*8 + q*2;
          float bb0 = b2s[cb], bb1 = b2s[cb+1];
          part0 += fast_tanh(d[nt][0] + bb0) * dXs[row0*DXPR + cb]
                 + fast_tanh(d[nt][1] + bb1) * dXs[row0*DXPR + cb + 1];
          part1 += fast_tanh(d[nt][2] + bb0) * dXs[row1*DXPR + cb]
                 + fast_tanh(d[nt][3] + bb1) * dXs[row1*DXPR + cb + 1];
        }
        part0 += __shfl_xor_sync(0xffffffffu, part0, 1);
        part0 += __shfl_xor_sync(0xffffffffu, part0, 2);
        part1 += __shfl_xor_sync(0xffffffffu, part1, 1);
        part1 += __shfl_xor_sync(0xffffffffu, part1, 2);
        if (q == 0) {
          __stcg(&g_k[s][row0*NH + bid], part0);
          __stcg(&g_k[s][row1*NH + bid], part1);
        }
      }
      // publish k-ready
      __syncthreads();
      ++seq;
      if (tid == 0) { __threadfence(); st_u32_cg(&g_flags[bid*32], seq); }
    }
    if (exit_all) break;

    // ======== phase C : accept/reject + FSAL + next-step scal ========
    {
      const float t = tcur, dtv = scal[1];
      float k7v = 0.f;
      if (tid < NH) {
        pollflag(tid, seq);   // k(6) column tid ready (own producer)
        int h = tid;
        float k1 = __ldcg(&g_k[0][bid*NH+h]);
        float k3 = __ldcg(&g_k[2][bid*NH+h]);
        float k4 = __ldcg(&g_k[3][bid*NH+h]);
        float k5 = __ldcg(&g_k[4][bid*NH+h]);
        float k6 = __ldcg(&g_k[5][bid*NH+h]);
        float k7 = __ldcg(&g_k[6][bid*NH+h]);
        k7v = k7;
        float ev = dt_c * (E0*k1 + E2*k3 + E3*k4 + E4*k5 + E5*k6 + E6*k7);
        float sc = 1e-3f + 1e-3f * fmaxf(fabsf(yreg), fabsf(ynew_r));
        float e = ev / sc;
        float e2v = e*e;
        #pragma unroll
        for (int o = 16; o > 0; o >>= 1) e2v += __shfl_down_sync(0xffffffffu, e2v, o);
        if ((tid & 31) == 0) red[tid >> 5] = e2v;
      }
      __syncthreads();
      if (tid == 0) {
        float ssum = red[0] + red[1] + red[2] + red[3];
        float err = sqrtf(ssum * (1.f/(float)NH));
        bool accept = (err <= 1.0f);
        float fac = 0.9f * powf(fmaxf(err, 1e-9f), -0.2f);
        fac = fminf(fmaxf(fac, 0.2f), 10.f);
        bool done = (t >= tEnd - 1e-8f);
        bool adv = accept && !done;
        float t_new = adv ? (t + dt_c) : t;
        float dt_new = done ? dtv : (dt_c * fac);
        scal[0] = t_new;
        scal[1] = dt_new;
        scal[2] = fminf(dt_new, tEnd - t_new);
        scal[3] = adv ? 1.f : 0.f;
        if (!counted && t_new >= tEnd - 1e-8f) {
          atomicAdd(&g_ndone, 1u);
          counted = true;
        }
      }
      __syncthreads();
      if (tid < NH && scal[3] != 0.f) {
        yreg = ynew_r;
        Ycur[tid] = ynew_r;
        __stcg(&g_k[0][bid*NH + tid], k7v);   // FSAL
      }
      __syncthreads();
    }
  }

  if (tid < NO) {
    float acc = lin_b[tid];
    #pragma unroll 4
    for (int h = 0; h < NH; h++)
      acc = fmaf(lin_w[tid*NH + h], Ycur[h], acc);
    out[bid*NO + tid] = acc;
  }
}

extern "C" void kernel_launch(void* const* d_in, const int* in_sizes, int n_in,
                              void* d_out, int out_size) {
  const float* ts    = (const float*)d_in[0];
  const float* xs    = (const float*)d_in[1];
  const float* W1    = (const float*)d_in[2];
  const float* b1    = (const float*)d_in[3];
  const float* W2    = (const float*)d_in[4];
  const float* b2    = (const float*)d_in[5];
  const float* lin_w = (const float*)d_in[6];
  const float* lin_b = (const float*)d_in[7];
  float* out = (float*)d_out;
  cudaFuncSetAttribute(cde_kernel, cudaFuncAttributeMaxDynamicSharedMemorySize, SMEM_BYTES);
  cde_kernel<<<NCTA, NTHR, SMEM_BYTES>>>(ts, xs, W1, b1, W2, b2, lin_w, lin_b, out);
}

// round 15
// speedup vs baseline: 1.3606x; 1.3606x over previous
#include <cuda_runtime.h>
#include <cuda_bf16.h>
#include <cstdint>

#define NB 128
#define NT 128
#define NC 32
#define NH 128
#define NO 10
#define NCTA 128
#define NTHR 512
#define MAXSTEPS 64

#define W1PR 132
#define W2PR 68
#define H1PR 68
#define DXPR 36
#define OFF_W1S 0            // 16896
#define OFF_W2HI 16896       // +2176
#define OFF_W2LO 19072       // +2176
#define OFF_H1HI 21248       // +8704
#define OFF_H1LO 29952       // +8704
#define OFF_DXS 38656        // +4608
#define OFF_RED 43264        // +512
#define OFF_TS  43776        // +128
#define OFF_B1  43904        // +128
#define OFF_B2  44032        // +32
#define OFF_YS  44064        // +128
#define OFF_YC  44192        // +128
#define OFF_SC  44320        // +8
#define SMEM_FLOATS 44328
#define SMEM_BYTES (SMEM_FLOATS * 4)   // 177312 B

__device__ __align__(16) float g_k[7][NB*NH];
__device__ __align__(16) unsigned g_H1hi[NB*64];
__device__ __align__(16) unsigned g_H1lo[NB*64];
__device__ __align__(16) float g_dX[7][NB*NC];
__device__ __align__(128) unsigned g_flags[NCTA*32];
__device__ unsigned g_ndone;

__constant__ float A_TAB[7][6] = {
  {0.f,0.f,0.f,0.f,0.f,0.f},
  {(float)(1.0/5.0),0.f,0.f,0.f,0.f,0.f},
  {(float)(3.0/40.0),(float)(9.0/40.0),0.f,0.f,0.f,0.f},
  {(float)(44.0/45.0),(float)(-56.0/15.0),(float)(32.0/9.0),0.f,0.f,0.f},
  {(float)(19372.0/6561.0),(float)(-25360.0/2187.0),(float)(64448.0/6561.0),(float)(-212.0/729.0),0.f,0.f},
  {(float)(9017.0/3168.0),(float)(-355.0/33.0),(float)(46732.0/5247.0),(float)(49.0/176.0),(float)(-5103.0/18656.0),0.f},
  {(float)(35.0/384.0),0.f,(float)(500.0/1113.0),(float)(125.0/192.0),(float)(-2187.0/6784.0),(float)(11.0/84.0)},
};
__constant__ float C_TAB[7] = {0.f,(float)(1.0/5.0),(float)(3.0/10.0),(float)(4.0/5.0),(float)(8.0/9.0),1.f,1.f};

#define E0 ((float)(71.0/57600.0))
#define E2 ((float)(-71.0/16695.0))
#define E3 ((float)(71.0/1920.0))
#define E4 ((float)(-17253.0/339200.0))
#define E5 ((float)(22.0/525.0))
#define E6 ((float)(-1.0/40.0))

__device__ __forceinline__ unsigned ld_u32_cg(const unsigned* p) {
  unsigned v; asm volatile("ld.global.cg.u32 %0, [%1];" : "=r"(v) : "l"(p)); return v;
}
__device__ __forceinline__ unsigned ld_acq(const unsigned* p) {
  unsigned v; asm volatile("ld.acquire.gpu.global.u32 %0, [%1];" : "=r"(v) : "l"(p)); return v;
}
__device__ __forceinline__ void st_u32_cg(unsigned* p, unsigned v) {
  asm volatile("st.global.cg.u32 [%0], %1;" :: "l"(p), "r"(v) : "memory");
}
__device__ __forceinline__ float fast_tanh(float x) {
  x = fminf(fmaxf(x, -9.f), 9.f);
  float e = __expf(2.f * x);
  return __fdividef(e - 1.f, e + 1.f);
}
__device__ __forceinline__ uint32_t pack_bf16x2(float e0, float e1) {
  uint32_t d;
  asm("cvt.rn.bf16x2.f32 %0, %1, %2;" : "=r"(d) : "f"(e1), "f"(e0));
  return d;
}
__device__ __forceinline__ uint32_t smem_u32(const void* p) {
  uint32_t a;
  asm("{ .reg .u64 t; cvta.to.shared.u64 t, %1; cvt.u32.u64 %0, t; }" : "=r"(a) : "l"(p));
  return a;
}
__device__ __forceinline__ void mma_bf16(float* d, uint32_t a0, uint32_t a1, uint32_t a2, uint32_t a3,
                                         uint32_t b0, uint32_t b1) {
  asm volatile(
    "mma.sync.aligned.m16n8k16.row.col.f32.bf16.bf16.f32 "
    "{%0,%1,%2,%3}, {%4,%5,%6,%7}, {%8,%9}, {%0,%1,%2,%3};"
    : "+f"(d[0]), "+f"(d[1]), "+f"(d[2]), "+f"(d[3])
    : "r"(a0), "r"(a1), "r"(a2), "r"(a3), "r"(b0), "r"(b1));
}
__device__ __forceinline__ void ldmx4(uint32_t* r, uint32_t addr) {
  asm volatile("ldmatrix.sync.aligned.m8n8.x4.shared.b16 {%0,%1,%2,%3}, [%4];"
    : "=r"(r[0]), "=r"(r[1]), "=r"(r[2]), "=r"(r[3]) : "r"(addr));
}

// all-poll distributed barrier (monotone seq, replay-safe)
__device__ __forceinline__ void gbar(unsigned seq) {
  __syncthreads();
  const int tid = threadIdx.x;
  if (tid == 0) {
    __threadfence();
    st_u32_cg(&g_flags[blockIdx.x * 32], seq);
  }
  if (tid < NCTA) {
    while ((int)(ld_acq(&g_flags[tid * 32]) - seq) < 0) { }
  }
  __syncthreads();
}

__global__ __launch_bounds__(NTHR, 1)
void cde_kernel(const float* __restrict__ ts, const float* __restrict__ xs,
                const float* __restrict__ W1, const float* __restrict__ b1,
                const float* __restrict__ W2, const float* __restrict__ b2,
                const float* __restrict__ lin_w, const float* __restrict__ lin_b,
                float* __restrict__ out)
{
  extern __shared__ float sm[];
  float*    W1s  = sm + OFF_W1S;
  unsigned* W2hiS= (unsigned*)(sm + OFF_W2HI);
  unsigned* W2loS= (unsigned*)(sm + OFF_W2LO);
  unsigned* H1hiS= (unsigned*)(sm + OFF_H1HI);
  unsigned* H1loS= (unsigned*)(sm + OFF_H1LO);
  float*    dXs  = sm + OFF_DXS;
  float*    red  = sm + OFF_RED;
  float*    tss  = sm + OFF_TS;
  float*    b1s  = sm + OFF_B1;
  float*    b2s  = sm + OFF_B2;
  float*    Ysm  = sm + OFF_YS;
  float*    Ycur = sm + OFF_YC;
  float*    scal = sm + OFF_SC;

  const int tid = threadIdx.x;
  const int bid = blockIdx.x;
  const int wid = tid >> 5;
  const int lane = tid & 31;
  const int g = lane >> 2;
  const int q = lane & 3;
  const int mwid = wid & 7;        // m-tile index (shared by warp pair)
  const int nhalf = wid >> 3;      // 0: c 0..15, 1: c 16..31
  const uint32_t smb = smem_u32(sm);

  const unsigned base_nd = ld_u32_cg(&g_ndone);
  unsigned seq = ld_u32_cg(&g_flags[bid * 32]);

  for (int i = tid; i < NH*NH; i += NTHR) { int h = i >> 7, k = i & 127; W1s[h*W1PR + k] = W1[i]; }
  for (int i = tid; i < 32*64; i += NTHR) {
    int c = i >> 6, kq = i & 63;
    float w0 = W2[bid*32*NH + c*NH + kq*2];
    float w1 = W2[bid*32*NH + c*NH + kq*2 + 1];
    __nv_bfloat16 h0 = __float2bfloat16(w0), h1 = __float2bfloat16(w1);
    W2hiS[c*W2PR + kq] = pack_bf16x2(w0, w1);
    W2loS[c*W2PR + kq] = pack_bf16x2(w0 - __bfloat162float(h0), w1 - __bfloat162float(h1));
  }
  for (int i = tid; i < NT; i += NTHR) tss[i] = ts[i];
  for (int i = tid; i < NH; i += NTHR) b1s[i] = b1[i];
  if (tid < 32) b2s[tid] = b2[bid*32 + tid];
  if (tid < NH) Ycur[tid] = 0.f;
  if (tid == 0) {
    float t0 = ts[0], te = ts[NT-1];
    scal[0] = t0; scal[1] = 0.01f; scal[2] = fminf(0.01f, te - t0);
  }
  __syncthreads();
  const float tEnd = tss[NT-1];
  const float* xb = xs + (size_t)bid*NT*NC;

  const int lrow = mwid*16 + (lane & 7) + ((lane >> 3) & 1) * 8;
  const int lcol = ((lane >> 4) & 1) * 4;
  const uint32_t hibase = smb + (uint32_t)(OFF_H1HI + lrow*H1PR + lcol) * 4u;
  const uint32_t lobase = smb + (uint32_t)(OFF_H1LO + lrow*H1PR + lcol) * 4u;

  float yreg = 0.f;
  float ynew_r = 0.f;
  bool counted = false;
  bool exit_all = false;

  for (int step = 0; step < MAXSTEPS && !exit_all; step++) {
    const int sb = (step == 0) ? 0 : 1;   // FSAL
    const float tcur = scal[0];
    const float dt_c = scal[2];
    for (int s = sb; s < 7; s++) {
      // ======== phase A : CTA = batch ========
      if (s > sb) {
        for (int i = tid; i < (NB*NC)/4; i += NTHR) {
          int b = i >> 3, c4 = (i & 7) * 4;
          float4 u = __ldcg((const float4*)&g_dX[s][b*NC + c4]);
          *(float4*)&dXs[b*DXPR + c4] = u;
        }
      }
      if (tid < NH) {
        float ysv;
        if (s == 0) ysv = yreg;
        else {
          float kv[6];
          #pragma unroll
          for (int j = 0; j < 6; j++)
            kv[j] = (j < s) ? __ldcg(&g_k[j][bid*NH + tid]) : 0.f;
          float acc = A_TAB[s][0] * kv[0];
          #pragma unroll
          for (int j = 1; j < 6; j++)
            acc = fmaf(A_TAB[s][j], kv[j], acc);
          ysv = yreg + dt_c * acc;
        }
        Ysm[tid] = ysv;
        if (s == 6) ynew_r = ysv;
      } else if (s == sb) {
        for (int i = tid - 128; i < (7 - sb) * NC; i += (NTHR - 128)) {
          int sp = sb + i / NC;
          int c = i % NC;
          float tq = tcur + C_TAB[sp] * dt_c;
          int lo = 0, hi = NT;
          while (lo < hi) { int mid = (lo + hi) >> 1; if (tss[mid] <= tq) lo = mid + 1; else hi = mid; }
          int idx = lo - 1; if (idx < 0) idx = 0; if (idx > NT-2) idx = NT-2;
          float t0 = tss[idx], t1 = tss[idx+1];
          float hh = t1 - t0;
          float sfr = (tq - t0) / hh;
          float dh00 = 6.f*sfr*sfr - 6.f*sfr;
          float dh10 = 3.f*sfr*sfr - 4.f*sfr + 1.f;
          float dh11 = 3.f*sfr*sfr - 2.f*sfr;
          float x0 = __ldg(&xb[idx*NC + c]);
          float x1 = __ldg(&xb[(idx+1)*NC + c]);
          float mi1 = (x1 - x0) / hh;
          float mi;
          if (idx == 0) mi = (x1 - x0) / (tss[1] - tss[0]);
          else { float xm1 = __ldg(&xb[(idx-1)*NC + c]); mi = (x0 - xm1) / (tss[idx] - tss[idx-1]); }
          float dx = (dh00*x0 - dh00*x1) / hh + dh10*mi + dh11*mi1;
          __stcg(&g_dX[sp][bid*NC + c], dx);
        }
      }
      __syncthreads();
      {
        // W1 matvec: 4-way split-k over 512 threads
        int h = tid & 127;
        int quarter = tid >> 7;          // 0..3
        const int kb = quarter * 32;
        float a0=0.f,a1=0.f,a2=0.f,a3=0.f;
        const float* wrow = &W1s[h*W1PR + kb];
        #pragma unroll 4
        for (int k = 0; k < 32; k += 4) {
          float4 wv = *(const float4*)&wrow[k];
          float4 yv = *(const float4*)&Ysm[kb + k];
          a0 = fmaf(wv.x, yv.x, a0);
          a1 = fmaf(wv.y, yv.y, a1);
          a2 = fmaf(wv.z, yv.z, a2);
          a3 = fmaf(wv.w, yv.w, a3);
        }
        red[quarter*NH + h] = (a0+a1)+(a2+a3);
      }
      __syncthreads();
      if (tid < 64) {
        float f0 = fmaxf(b1s[2*tid]   + ((red[2*tid]   + red[NH + 2*tid])   + (red[2*NH + 2*tid]   + red[3*NH + 2*tid])),   0.f);
        float f1 = fmaxf(b1s[2*tid+1] + ((red[2*tid+1] + red[NH + 2*tid+1]) + (red[2*NH + 2*tid+1] + red[3*NH + 2*tid+1])), 0.f);
        uint32_t hi = pack_bf16x2(f0, f1);
        __nv_bfloat162 hb = *reinterpret_cast<__nv_bfloat162*>(&hi);
        uint32_t lo = pack_bf16x2(f0 - __bfloat162float(hb.x), f1 - __bfloat162float(hb.y));
        st_u32_cg(&g_H1hi[bid*64 + tid], hi);
        st_u32_cg(&g_H1lo[bid*64 + tid], lo);
      }
      gbar(++seq);

      if (s == sb) {
        if (tid == 0) scal[4] = (float)(ld_u32_cg(&g_ndone) - base_nd);
        __syncthreads();
        if (scal[4] == (float)NB) { exit_all = true; break; }
      }

      // ======== phase B : CTA = h, ldmatrix + bf16 HMMA (16 warps) ========
      {
        for (int i = tid; i < 128*16; i += NTHR) {
          int row = i >> 4, c4 = (i & 15) * 4;
          uint4 u = __ldcg((const uint4*)&g_H1hi[row*64 + c4]);
          *(uint4*)&H1hiS[row*H1PR + c4] = u;
          uint4 v = __ldcg((const uint4*)&g_H1lo[row*64 + c4]);
          *(uint4*)&H1loS[row*H1PR + c4] = v;
        }
        if (s == sb) {
          for (int i = tid; i < (NB*NC)/4; i += NTHR) {
            int b = i >> 3, c4 = (i & 7) * 4;
            float4 u = __ldcg((const float4*)&g_dX[s][b*NC + c4]);
            *(float4*)&dXs[b*DXPR + c4] = u;
          }
        }
        __syncthreads();

        const int mb = mwid * 16;
        const int nt0 = nhalf * 2;
        float d[2][4];
        #pragma unroll
        for (int j = 0; j < 2; j++)
          #pragma unroll
          for (int r = 0; r < 4; r++) d[j][r] = 0.f;

        #pragma unroll
        for (int kk = 0; kk < 8; kk++) {
          const int kq = kk*8 + q;
          uint32_t ah[4], al[4];
          ldmx4(ah, hibase + (uint32_t)kk * 32u);
          ldmx4(al, lobase + (uint32_t)kk * 32u);
          #pragma unroll
          for (int j = 0; j < 2; j++) {
            const int c = (nt0 + j)*8 + g;
            uint32_t bh0 = W2hiS[c*W2PR + kq];
            uint32_t bh1 = W2hiS[c*W2PR + kq + 4];
            uint32_t bl0 = W2loS[c*W2PR + kq];
            uint32_t bl1 = W2loS[c*W2PR + kq + 4];
            mma_bf16(d[j], ah[0], ah[1], ah[2], ah[3], bh0, bh1);
            mma_bf16(d[j], al[0], al[1], al[2], al[3], bh0, bh1);
            mma_bf16(d[j], ah[0], ah[1], ah[2], ah[3], bl0, bl1);
          }
        }

        float part0 = 0.f, part1 = 0.f;
        const int row0 = mb + g, row1 = mb + g + 8;
        #pragma unroll
        for (int j = 0; j < 2; j++) {
          const int cb = (nt0 + j)*8 + q*2;
          float bb0 = b2s[cb], bb1 = b2s[cb+1];
          part0 += fast_tanh(d[j][0] + bb0) * dXs[row0*DXPR + cb]
                 + fast_tanh(d[j][1] + bb1) * dXs[row0*DXPR + cb + 1];
          part1 += fast_tanh(d[j][2] + bb0) * dXs[row1*DXPR + cb]
                 + fast_tanh(d[j][3] + bb1) * dXs[row1*DXPR + cb + 1];
        }
        part0 += __shfl_xor_sync(0xffffffffu, part0, 1);
        part0 += __shfl_xor_sync(0xffffffffu, part0, 2);
        part1 += __shfl_xor_sync(0xffffffffu, part1, 1);
        part1 += __shfl_xor_sync(0xffffffffu, part1, 2);
        if (q == 0) {
          red[nhalf*NB + row0] = part0;
          red[nhalf*NB + row1] = part1;
        }
        __syncthreads();
        if (tid < NB) {
          float kv = red[tid] + red[NB + tid];
          __stcg(&g_k[s][tid*NH + bid], kv);
        }
      }
      gbar(++seq);
    }
    if (exit_all) break;

    // ======== phase C : accept/reject + FSAL + next-step scal ========
    {
      const float t = tcur, dtv = scal[1];
      float k7v = 0.f;
      if (tid < NH) {
        int h = tid;
        float k1 = __ldcg(&g_k[0][bid*NH+h]);
        float k3 = __ldcg(&g_k[2][bid*NH+h]);
        float k4 = __ldcg(&g_k[3][bid*NH+h]);
        float k5 = __ldcg(&g_k[4][bid*NH+h]);
        float k6 = __ldcg(&g_k[5][bid*NH+h]);
        float k7 = __ldcg(&g_k[6][bid*NH+h]);
        k7v = k7;
        float ev = dt_c * (E0*k1 + E2*k3 + E3*k4 + E4*k5 + E5*k6 + E6*k7);
        float sc = 1e-3f + 1e-3f * fmaxf(fabsf(yreg), fabsf(ynew_r));
        float e = ev / sc;
        float e2v = e*e;
        #pragma unroll
        for (int o = 16; o > 0; o >>= 1) e2v += __shfl_down_sync(0xffffffffu, e2v, o);
        if ((tid & 31) == 0) red[tid >> 5] = e2v;
      }
      __syncthreads();
      if (tid == 0) {
        float ssum = red[0] + red[1] + red[2] + red[3];
        float err = sqrtf(ssum * (1.f/(float)NH));
        bool accept = (err <= 1.0f);
        float fac = 0.9f * powf(fmaxf(err, 1e-9f), -0.2f);
        fac = fminf(fmaxf(fac, 0.2f), 10.f);
        bool done = (t >= tEnd - 1e-8f);
        bool adv = accept && !done;
        float t_new = adv ? (t + dt_c) : t;
        float dt_new = done ? dtv : (dt_c * fac);
        scal[0] = t_new;
        scal[1] = dt_new;
        scal[2] = fminf(dt_new, tEnd - t_new);
        scal[3] = adv ? 1.f : 0.f;
        if (!counted && t_new >= tEnd - 1e-8f) {
          atomicAdd(&g_ndone, 1u);
          counted = true;
        }
      }
      __syncthreads();
      if (tid < NH && scal[3] != 0.f) {
        yreg = ynew_r;
        Ycur[tid] = ynew_r;
        __stcg(&g_k[0][bid*NH + tid], k7v);   // FSAL
      }
      __syncthreads();
    }
  }

  if (tid < NO) {
    float acc = lin_b[tid];
    #pragma unroll 4
    for (int h = 0; h < NH; h++)
      acc = fmaf(lin_w[tid*NH + h], Ycur[h], acc);
    out[bid*NO + tid] = acc;
  }
}

extern "C" void kernel_launch(void* const* d_in, const int* in_sizes, int n_in,
                              void* d_out, int out_size) {
  const float* ts    = (const float*)d_in[0];
  const float* xs    = (const float*)d_in[1];
  const float* W1    = (const float*)d_in[2];
  const float* b1    = (const float*)d_in[3];
  const float* W2    = (const float*)d_in[4];
  const float* b2    = (const float*)d_in[5];
  const float* lin_w = (const float*)d_in[6];
  const float* lin_b = (const float*)d_in[7];
  float* out = (float*)d_out;
  cudaFuncSetAttribute(cde_kernel, cudaFuncAttributeMaxDynamicSharedMemorySize, SMEM_BYTES);
  cde_kernel<<<NCTA, NTHR, SMEM_BYTES>>>(ts, xs, W1, b1, W2, b2, lin_w, lin_b, out);
}